// round 1
// baseline (speedup 1.0000x reference)
#include <cuda_runtime.h>

#define NN 8192
#define MM 2048
#define DD 256
#define DHH 8
#define ROW_CAP 64
#define COL_CAP 128

// ---------------- scratch (static device globals; no allocation) -------------
__device__ float g_WX[NN * DHH];
__device__ float g_WE[MM * DHH];
__device__ float g_sx[NN];   // WX @ alpha_x[:dh]
__device__ float g_s2[NN];   // WX @ alpha_e[dh:]
__device__ float g_se[MM];   // WE @ alpha_x[dh:]
__device__ float g_s1[MM];   // WE @ alpha_e[:dh]
__device__ int   g_row_cnt[NN];
__device__ int   g_col_cnt[MM];
__device__ int   g_row_edges[NN * ROW_CAP];
__device__ int   g_col_nodes[MM * COL_CAP];
__device__ float g_row_max[NN], g_row_sum[NN];
__device__ float g_col_max[MM], g_col_sum[MM];
__device__ float g_Enew[MM * DHH];
__device__ float g_empty_wx[DHH];  // sum of WX rows of edge-less nodes
__device__ float g_empty_en[DHH];  // sum of E_new rows of node-less edges

__device__ __forceinline__ float leaky(float x) {
    return x >= 0.f ? x : 0.2f * x;
}
__device__ __forceinline__ float elu(float x) {
    return x > 0.f ? x : expm1f(x);
}

// ---------------- K0: zero counters ------------------------------------------
__global__ void k_init() {
    int t = blockIdx.x * blockDim.x + threadIdx.x;
    if (t < NN) g_row_cnt[t] = 0;
    if (t < MM) g_col_cnt[t] = 0;
    if (t < DHH) { g_empty_wx[t] = 0.f; g_empty_en[t] = 0.f; }
}

// ---------------- K1: projection + attention-logit dots ----------------------
// isE==0: rows of X -> g_WX, g_sx (ax[:8]), g_s2 (ae[8:])
// isE==1: rows of E -> g_WE, g_se (ax[8:]), g_s1 (ae[:8])
__global__ void k_proj(const float* __restrict__ A,
                       const float* __restrict__ W,
                       const float* __restrict__ alpha_x,
                       const float* __restrict__ alpha_e,
                       int rows, int isE) {
    __shared__ float sW[DD * DHH];
    __shared__ float sv1[DHH], sv2[DHH];
    for (int j = threadIdx.x; j < DD * DHH; j += blockDim.x) sW[j] = W[j];
    if (threadIdx.x < DHH) {
        sv1[threadIdx.x] = isE ? alpha_x[DHH + threadIdx.x] : alpha_x[threadIdx.x];
        sv2[threadIdx.x] = isE ? alpha_e[threadIdx.x]       : alpha_e[DHH + threadIdx.x];
    }
    __syncthreads();
    int i = blockIdx.x * blockDim.x + threadIdx.x;
    if (i >= rows) return;

    float acc[DHH];
#pragma unroll
    for (int d = 0; d < DHH; d++) acc[d] = 0.f;

    const float4* Ar = reinterpret_cast<const float4*>(A + (size_t)i * DD);
#pragma unroll 4
    for (int j4 = 0; j4 < DD / 4; j4++) {
        float4 x = Ar[j4];
        int j = 4 * j4;
#pragma unroll
        for (int d = 0; d < DHH; d++) acc[d] += x.x * sW[(j + 0) * DHH + d];
#pragma unroll
        for (int d = 0; d < DHH; d++) acc[d] += x.y * sW[(j + 1) * DHH + d];
#pragma unroll
        for (int d = 0; d < DHH; d++) acc[d] += x.z * sW[(j + 2) * DHH + d];
#pragma unroll
        for (int d = 0; d < DHH; d++) acc[d] += x.w * sW[(j + 3) * DHH + d];
    }

    float d1 = 0.f, d2 = 0.f;
#pragma unroll
    for (int d = 0; d < DHH; d++) { d1 += acc[d] * sv1[d]; d2 += acc[d] * sv2[d]; }

    if (isE) {
#pragma unroll
        for (int d = 0; d < DHH; d++) g_WE[i * DHH + d] = acc[d];
        g_se[i] = d1; g_s1[i] = d2;
    } else {
#pragma unroll
        for (int d = 0; d < DHH; d++) g_WX[i * DHH + d] = acc[d];
        g_sx[i] = d1; g_s2[i] = d2;
    }
}

// ---------------- K2: single streaming pass over dense H ---------------------
__global__ void k_scan(const float* __restrict__ H) {
    const int total4 = NN * MM / 4;
    int t = blockIdx.x * blockDim.x + threadIdx.x;
    int stride = gridDim.x * blockDim.x;
    const float4* H4 = reinterpret_cast<const float4*>(H);
    for (int idx = t; idx < total4; idx += stride) {
        float4 h = H4[idx];
        if (h.x > 0.f || h.y > 0.f || h.z > 0.f || h.w > 0.f) {
            int base = idx * 4;
            float v[4] = {h.x, h.y, h.z, h.w};
#pragma unroll
            for (int c = 0; c < 4; c++) {
                if (v[c] > 0.f) {
                    int lin = base + c;
                    int i = lin >> 11;        // / MM (2048)
                    int k = lin & (MM - 1);   // % MM
                    int p = atomicAdd(&g_row_cnt[i], 1);
                    if (p < ROW_CAP) g_row_edges[i * ROW_CAP + p] = k;
                    int q = atomicAdd(&g_col_cnt[k], 1);
                    if (q < COL_CAP) g_col_nodes[k * COL_CAP + q] = i;
                }
            }
        }
    }
}

// ---------------- K3: per-node online softmax stats + empty-node sum ---------
__global__ void k_nodestats() {
    int i = blockIdx.x * blockDim.x + threadIdx.x;
    if (i >= NN) return;
    int cnt = min(g_row_cnt[i], ROW_CAP);
    if (cnt == 0) {
#pragma unroll
        for (int d = 0; d < DHH; d++) atomicAdd(&g_empty_wx[d], g_WX[i * DHH + d]);
        return;
    }
    float sxi = g_sx[i];
    float m = -3.0e38f, s = 0.f;
    for (int j = 0; j < cnt; j++) {
        int k = g_row_edges[i * ROW_CAP + j];
        float v = leaky(sxi + g_se[k]);
        if (v > m) { s = s * __expf(m - v) + 1.f; m = v; }
        else       { s += __expf(v - m); }
    }
    g_row_max[i] = m; g_row_sum[i] = s;
}

// ---------------- K4: E_new = elu(att^T @ WX), warp per edge -----------------
__global__ void k_enew() {
    int gid = blockIdx.x * blockDim.x + threadIdx.x;
    int k = gid >> 5;
    int lane = threadIdx.x & 31;
    if (k >= MM) return;
    int cnt = min(g_col_cnt[k], COL_CAP);
    float sek = g_se[k];
    float acc[DHH];
#pragma unroll
    for (int d = 0; d < DHH; d++) acc[d] = 0.f;
    for (int j = lane; j < cnt; j += 32) {
        int i = g_col_nodes[k * COL_CAP + j];
        float v = leaky(g_sx[i] + sek);
        float w = __expf(v - g_row_max[i]) / g_row_sum[i];
        const float4* wx = reinterpret_cast<const float4*>(&g_WX[i * DHH]);
        float4 a = wx[0], b = wx[1];
        acc[0] += w * a.x; acc[1] += w * a.y; acc[2] += w * a.z; acc[3] += w * a.w;
        acc[4] += w * b.x; acc[5] += w * b.y; acc[6] += w * b.z; acc[7] += w * b.w;
    }
#pragma unroll
    for (int d = 0; d < DHH; d++)
#pragma unroll
        for (int off = 16; off > 0; off >>= 1)
            acc[d] += __shfl_xor_sync(0xffffffffu, acc[d], off);
    if (lane == 0) {
        const float invM = 1.f / MM;
#pragma unroll
        for (int d = 0; d < DHH; d++) {
            float o = acc[d] + invM * g_empty_wx[d];
            g_Enew[k * DHH + d] = elu(o);
        }
    }
}

// ---------------- K5: per-edge softmax stats + empty-edge sum ----------------
__global__ void k_edgestats() {
    int k = blockIdx.x * blockDim.x + threadIdx.x;
    if (k >= MM) return;
    int cnt = min(g_col_cnt[k], COL_CAP);
    if (cnt == 0) {
#pragma unroll
        for (int d = 0; d < DHH; d++) atomicAdd(&g_empty_en[d], g_Enew[k * DHH + d]);
        return;
    }
    float s1k = g_s1[k];
    float m = -3.0e38f, s = 0.f;
    for (int j = 0; j < cnt; j++) {
        int i = g_col_nodes[k * COL_CAP + j];
        float v = leaky(s1k + g_s2[i]);
        if (v > m) { s = s * __expf(m - v) + 1.f; m = v; }
        else       { s += __expf(v - m); }
    }
    g_col_max[k] = m; g_col_sum[k] = s;
}

// ---------------- K6: X_new = elu(att_e^T @ E_new), thread per node ----------
__global__ void k_xnew(float* __restrict__ out) {
    int i = blockIdx.x * blockDim.x + threadIdx.x;
    if (i >= NN) return;
    int cnt = min(g_row_cnt[i], ROW_CAP);
    float s2i = g_s2[i];
    float acc[DHH];
#pragma unroll
    for (int d = 0; d < DHH; d++) acc[d] = 0.f;
    for (int j = 0; j < cnt; j++) {
        int k = g_row_edges[i * ROW_CAP + j];
        float v = leaky(g_s1[k] + s2i);
        float w = __expf(v - g_col_max[k]) / g_col_sum[k];
        const float4* en = reinterpret_cast<const float4*>(&g_Enew[k * DHH]);
        float4 a = en[0], b = en[1];
        acc[0] += w * a.x; acc[1] += w * a.y; acc[2] += w * a.z; acc[3] += w * a.w;
        acc[4] += w * b.x; acc[5] += w * b.y; acc[6] += w * b.z; acc[7] += w * b.w;
    }
    const float invN = 1.f / NN;
#pragma unroll
    for (int d = 0; d < DHH; d++) {
        float o = acc[d] + invN * g_empty_en[d];
        out[i * DHH + d] = elu(o);
    }
}

// -----------------------------------------------------------------------------
extern "C" void kernel_launch(void* const* d_in, const int* in_sizes, int n_in,
                              void* d_out, int out_size) {
    const float* X  = (const float*)d_in[0];  // [8192, 256]
    const float* E  = (const float*)d_in[1];  // [2048, 256]
    const float* H  = (const float*)d_in[2];  // [8192, 2048]
    const float* W  = (const float*)d_in[3];  // [256, 8]
    const float* ax = (const float*)d_in[4];  // [16, 1]
    const float* ae = (const float*)d_in[5];  // [16, 1]
    float* out = (float*)d_out;               // [8192, 8]

    k_init<<<(NN + 255) / 256, 256>>>();
    k_proj<<<(NN + 255) / 256, 256>>>(X, W, ax, ae, NN, 0);
    k_proj<<<(MM + 255) / 256, 256>>>(E, W, ax, ae, MM, 1);
    k_scan<<<2048, 256>>>(H);
    k_nodestats<<<(NN + 255) / 256, 256>>>();
    k_enew<<<(MM * 32 + 255) / 256, 256>>>();
    k_edgestats<<<(MM + 255) / 256, 256>>>();
    k_xnew<<<(NN + 255) / 256, 256>>>(out);
}

// round 2
// speedup vs baseline: 1.6801x; 1.6801x over previous
#include <cuda_runtime.h>

#define NN 8192
#define MM 2048
#define DD 256
#define DHH 8
#define ROW_CAP 64
#define COL_CAP 128
#define PROJ_BLOCKS 40          // (NN+MM)/256
#define SCAN_BLOCKS 2048
#define SCAN_ITERS 8            // NN*MM/4 / (SCAN_BLOCKS*256)

// ---------------- scratch (static device globals; no allocation) -------------
__device__ float g_WX[NN * DHH];
__device__ float g_sx[NN];   // WX @ alpha_x[:dh]
__device__ float g_s2[NN];   // WX @ alpha_e[dh:]
__device__ float g_se[MM];   // WE @ alpha_x[dh:]
__device__ float g_s1[MM];   // WE @ alpha_e[:dh]
__device__ int   g_row_cnt[NN];
__device__ int   g_col_cnt[MM];
__device__ int   g_row_edges[NN * ROW_CAP];
__device__ int   g_col_nodes[MM * COL_CAP];
__device__ float g_row_max[NN], g_row_sum[NN];
__device__ float g_col_max[MM], g_col_sum[MM];
__device__ float g_Enew[MM * DHH];
__device__ float g_empty_wx[DHH];
__device__ float g_empty_en[DHH];

__device__ __forceinline__ float leaky(float x) { return x >= 0.f ? x : 0.2f * x; }
__device__ __forceinline__ float elu(float x)   { return x > 0.f ? x : expm1f(x); }

// ---------------- K0: zero counters ------------------------------------------
__global__ void k_init() {
    int t = blockIdx.x * blockDim.x + threadIdx.x;
    if (t < NN) g_row_cnt[t] = 0;
    if (t < MM) g_col_cnt[t] = 0;
    if (t < DHH) { g_empty_wx[t] = 0.f; g_empty_en[t] = 0.f; }
}

// ---------------- K1: fused projection + H scan (independent block groups) ---
__global__ void k_main(const float* __restrict__ X, const float* __restrict__ E,
                       const float* __restrict__ H, const float* __restrict__ W,
                       const float* __restrict__ ax, const float* __restrict__ ae) {
    if (blockIdx.x >= PROJ_BLOCKS) {
        // ---- scan portion: fully unrolled, MLP=8 ----
        int t = (blockIdx.x - PROJ_BLOCKS) * blockDim.x + threadIdx.x;
        const int stride = SCAN_BLOCKS * 256;
        const uint4* H4 = reinterpret_cast<const uint4*>(H);
        uint4 v[SCAN_ITERS];
#pragma unroll
        for (int it = 0; it < SCAN_ITERS; it++) v[it] = H4[t + it * stride];
#pragma unroll
        for (int it = 0; it < SCAN_ITERS; it++) {
            uint4 h = v[it];
            if (h.x | h.y | h.z | h.w) {
                int base = (t + it * stride) * 4;
                unsigned c4[4] = {h.x, h.y, h.z, h.w};
#pragma unroll
                for (int c = 0; c < 4; c++) {
                    if (c4[c]) {
                        int lin = base + c;
                        int i = lin >> 11;        // / MM
                        int k = lin & (MM - 1);   // % MM
                        int p = atomicAdd(&g_row_cnt[i], 1);
                        if (p < ROW_CAP) g_row_edges[i * ROW_CAP + p] = k;
                        int q = atomicAdd(&g_col_cnt[k], 1);
                        if (q < COL_CAP) g_col_nodes[k * COL_CAP + q] = i;
                    }
                }
            }
        }
        return;
    }

    // ---- projection portion: rows 0..NN-1 -> X, NN..NN+MM-1 -> E ----
    __shared__ float sW[DD * DHH];
    __shared__ float sax[2 * DHH], sae[2 * DHH];
    for (int j = threadIdx.x; j < DD * DHH; j += blockDim.x) sW[j] = W[j];
    if (threadIdx.x < 2 * DHH) {
        sax[threadIdx.x] = ax[threadIdx.x];
        sae[threadIdx.x] = ae[threadIdx.x];
    }
    __syncthreads();

    int r = blockIdx.x * blockDim.x + threadIdx.x;   // 0..10239
    const float* src = (r < NN) ? (X + (size_t)r * DD)
                                : (E + (size_t)(r - NN) * DD);
    float acc[DHH];
#pragma unroll
    for (int d = 0; d < DHH; d++) acc[d] = 0.f;

    const float4* Ar = reinterpret_cast<const float4*>(src);
#pragma unroll 4
    for (int j4 = 0; j4 < DD / 4; j4++) {
        float4 x = Ar[j4];
        int j = 4 * j4;
#pragma unroll
        for (int d = 0; d < DHH; d++) acc[d] += x.x * sW[(j + 0) * DHH + d];
#pragma unroll
        for (int d = 0; d < DHH; d++) acc[d] += x.y * sW[(j + 1) * DHH + d];
#pragma unroll
        for (int d = 0; d < DHH; d++) acc[d] += x.z * sW[(j + 2) * DHH + d];
#pragma unroll
        for (int d = 0; d < DHH; d++) acc[d] += x.w * sW[(j + 3) * DHH + d];
    }

    if (r < NN) {
        float d1 = 0.f, d2 = 0.f;
#pragma unroll
        for (int d = 0; d < DHH; d++) {
            d1 += acc[d] * sax[d];          // alpha_x[:dh]
            d2 += acc[d] * sae[DHH + d];    // alpha_e[dh:]
            g_WX[r * DHH + d] = acc[d];
        }
        g_sx[r] = d1; g_s2[r] = d2;
    } else {
        int k = r - NN;
        float d1 = 0.f, d2 = 0.f;
#pragma unroll
        for (int d = 0; d < DHH; d++) {
            d1 += acc[d] * sax[DHH + d];    // alpha_x[dh:]
            d2 += acc[d] * sae[d];          // alpha_e[:dh]
        }
        g_se[k] = d1; g_s1[k] = d2;
    }
}

// ---------------- K2: per-node softmax stats + empty-node sum ----------------
__global__ void k_nodestats() {
    int i = blockIdx.x * blockDim.x + threadIdx.x;
    if (i >= NN) return;
    int cnt = min(g_row_cnt[i], ROW_CAP);
    if (cnt == 0) {
#pragma unroll
        for (int d = 0; d < DHH; d++) atomicAdd(&g_empty_wx[d], g_WX[i * DHH + d]);
        return;
    }
    float sxi = g_sx[i];
    float m = -3.0e38f, s = 0.f;
    for (int j = 0; j < cnt; j++) {
        int k = g_row_edges[i * ROW_CAP + j];
        float v = leaky(sxi + g_se[k]);
        if (v > m) { s = s * __expf(m - v) + 1.f; m = v; }
        else       { s += __expf(v - m); }
    }
    g_row_max[i] = m; g_row_sum[i] = s;
}

// ---------------- K3: E_new + per-edge softmax stats, warp per edge ----------
__global__ void k_enew() {
    int gid = blockIdx.x * blockDim.x + threadIdx.x;
    int k = gid >> 5;
    int lane = threadIdx.x & 31;
    if (k >= MM) return;
    int cnt = min(g_col_cnt[k], COL_CAP);
    const float invM = 1.f / MM;

    if (cnt == 0) {
        // empty edge: E_new row is elu(invM * empty_wx); it feeds every node
        if (lane < DHH) {
            float o = elu(invM * g_empty_wx[lane]);
            g_Enew[k * DHH + lane] = o;
            atomicAdd(&g_empty_en[lane], o);
        }
        return;
    }

    float sek = g_se[k], s1k = g_s1[k];
    float m = -3.0e38f, s = 0.f;
    float acc[DHH];
#pragma unroll
    for (int d = 0; d < DHH; d++) acc[d] = 0.f;

    for (int j = lane; j < cnt; j += 32) {
        int i = g_col_nodes[k * COL_CAP + j];
        // edge-side softmax stats (for K4)
        float v2 = leaky(s1k + g_s2[i]);
        if (v2 > m) { s = s * __expf(m - v2) + 1.f; m = v2; }
        else        { s += __expf(v2 - m); }
        // node-side attention weight, aggregate WX
        float v = leaky(g_sx[i] + sek);
        float w = __expf(v - g_row_max[i]) / g_row_sum[i];
        const float4* wx = reinterpret_cast<const float4*>(&g_WX[i * DHH]);
        float4 a = wx[0], b = wx[1];
        acc[0] += w * a.x; acc[1] += w * a.y; acc[2] += w * a.z; acc[3] += w * a.w;
        acc[4] += w * b.x; acc[5] += w * b.y; acc[6] += w * b.z; acc[7] += w * b.w;
    }

    // warp reductions
    float M = m;
#pragma unroll
    for (int off = 16; off > 0; off >>= 1)
        M = fmaxf(M, __shfl_xor_sync(0xffffffffu, M, off));
    float sadj = s * __expf(m - M);
#pragma unroll
    for (int off = 16; off > 0; off >>= 1)
        sadj += __shfl_xor_sync(0xffffffffu, sadj, off);
#pragma unroll
    for (int d = 0; d < DHH; d++)
#pragma unroll
        for (int off = 16; off > 0; off >>= 1)
            acc[d] += __shfl_xor_sync(0xffffffffu, acc[d], off);

    if (lane == 0) {
        g_col_max[k] = M;
        g_col_sum[k] = sadj;
#pragma unroll
        for (int d = 0; d < DHH; d++)
            g_Enew[k * DHH + d] = elu(acc[d] + invM * g_empty_wx[d]);
    }
}

// ---------------- K4: X_new, thread per node ---------------------------------
__global__ void k_xnew(float* __restrict__ out) {
    int i = blockIdx.x * blockDim.x + threadIdx.x;
    if (i >= NN) return;
    int cnt = min(g_row_cnt[i], ROW_CAP);
    float s2i = g_s2[i];
    float acc[DHH];
#pragma unroll
    for (int d = 0; d < DHH; d++) acc[d] = 0.f;
    for (int j = 0; j < cnt; j++) {
        int k = g_row_edges[i * ROW_CAP + j];
        float v = leaky(g_s1[k] + s2i);
        float w = __expf(v - g_col_max[k]) / g_col_sum[k];
        const float4* en = reinterpret_cast<const float4*>(&g_Enew[k * DHH]);
        float4 a = en[0], b = en[1];
        acc[0] += w * a.x; acc[1] += w * a.y; acc[2] += w * a.z; acc[3] += w * a.w;
        acc[4] += w * b.x; acc[5] += w * b.y; acc[6] += w * b.z; acc[7] += w * b.w;
    }
    const float invN = 1.f / NN;
#pragma unroll
    for (int d = 0; d < DHH; d++)
        out[i * DHH + d] = elu(acc[d] + invN * g_empty_en[d]);
}

// -----------------------------------------------------------------------------
extern "C" void kernel_launch(void* const* d_in, const int* in_sizes, int n_in,
                              void* d_out, int out_size) {
    const float* X  = (const float*)d_in[0];
    const float* E  = (const float*)d_in[1];
    const float* H  = (const float*)d_in[2];
    const float* W  = (const float*)d_in[3];
    const float* ax = (const float*)d_in[4];
    const float* ae = (const float*)d_in[5];
    float* out = (float*)d_out;

    k_init<<<(NN + 255) / 256, 256>>>();
    k_main<<<PROJ_BLOCKS + SCAN_BLOCKS, 256>>>(X, E, H, W, ax, ae);
    k_nodestats<<<(NN + 255) / 256, 256>>>();
    k_enew<<<(MM * 32 + 255) / 256, 256>>>();
    k_xnew<<<(NN + 255) / 256, 256>>>(out);
}